// round 1
// baseline (speedup 1.0000x reference)
#include <cuda_runtime.h>
#include <math.h>

// Problem constants
#define T_TOK 8192
#define DIMSZ 512
#define HIDSZ 1024
#define NE    8
#define TOPK  2

// GEMM tile config
#define BM 64
#define BN 64
#define BK 16

// ---------------- device scratch (no allocations allowed) ----------------
__device__ int   g_count[NE];
__device__ int   g_list[NE][T_TOK];                    // slot ids (t*2+k) per expert
__device__ float g_p[T_TOK * TOPK];                    // gate value per slot
__device__ float g_h[(size_t)T_TOK * TOPK * HIDSZ];    // routed hidden activations, row = slot
__device__ float g_hs[(size_t)T_TOK * HIDSZ];          // shared-expert hidden, row = token
__device__ float g_ys[(size_t)T_TOK * TOPK * DIMSZ];   // routed outputs per slot

// ---------------- reset ----------------
__global__ void reset_counts_kernel() {
    if (threadIdx.x < NE) g_count[threadIdx.x] = 0;
}

// ---------------- router: scores, top-2, gates, expert lists ----------------
__global__ void router_kernel(const float* __restrict__ x,
                              const float* __restrict__ gw,
                              const float* __restrict__ biases) {
    int warp = (blockIdx.x * blockDim.x + threadIdx.x) >> 5;
    int lane = threadIdx.x & 31;
    if (warp >= T_TOK) return;
    const float* xt = x + (size_t)warp * DIMSZ;

    float sc[NE];
#pragma unroll
    for (int e = 0; e < NE; e++) sc[e] = 0.f;
    for (int i = lane; i < DIMSZ; i += 32) {
        float xv = xt[i];
#pragma unroll
        for (int e = 0; e < NE; e++) sc[e] += xv * gw[e * DIMSZ + i];
    }
#pragma unroll
    for (int e = 0; e < NE; e++) {
#pragma unroll
        for (int off = 16; off; off >>= 1)
            sc[e] += __shfl_xor_sync(0xffffffffu, sc[e], off);
    }
    if (lane != 0) return;

    // indices from biased scores (ties -> lower index, like jax top_k)
    float b[NE];
#pragma unroll
    for (int e = 0; e < NE; e++) b[e] = sc[e] + biases[e];
    int i0 = 0;
#pragma unroll
    for (int e = 1; e < NE; e++) if (b[e] > b[i0]) i0 = e;
    int i1 = (i0 == 0) ? 1 : 0;
#pragma unroll
    for (int e = 0; e < NE; e++) if (e != i0 && b[e] > b[i1]) i1 = e;

    // gate values = top-2 of UNBIASED scores
    int a0 = 0;
#pragma unroll
    for (int e = 1; e < NE; e++) if (sc[e] > sc[a0]) a0 = e;
    int a1 = (a0 == 0) ? 1 : 0;
#pragma unroll
    for (int e = 0; e < NE; e++) if (e != a0 && sc[e] > sc[a1]) a1 = e;

    float p0 = 1.f / (1.f + expf(-sc[a0]));
    float p1 = 1.f / (1.f + expf(-sc[a1]));
    float s = p0 + p1;
    p0 /= s; p1 /= s;

    int t = warp;
    int pos0 = atomicAdd(&g_count[i0], 1);
    g_list[i0][pos0] = t * 2 + 0;
    g_p[t * 2 + 0] = p0;
    int pos1 = atomicAdd(&g_count[i1], 1);
    g_list[i1][pos1] = t * 2 + 1;
    g_p[t * 2 + 1] = p1;
}

// ---------------- up projection: h = silu(x@W1) * (x@W3) ----------------
// routed=1: gathered rows from g_list[e], weights w1/w3 offset by expert, out -> g_h (row = slot)
// routed=0: identity rows (all tokens), weights = sw1/sw3 (z grid = 1), out -> g_hs (row = token)
__global__ __launch_bounds__(256) void ffn_up_kernel(const float* __restrict__ x,
                                                     const float* __restrict__ w1,
                                                     const float* __restrict__ w3,
                                                     int routed) {
    int e = blockIdx.z;
    int M;
    const int* lst = nullptr;
    if (routed) { M = g_count[e]; lst = g_list[e]; }
    else M = T_TOK;
    int row0 = blockIdx.x * BM;
    if (row0 >= M) return;
    const float* W1 = w1 + (size_t)e * DIMSZ * HIDSZ;
    const float* W3 = w3 + (size_t)e * DIMSZ * HIDSZ;
    int col0 = blockIdx.y * BN;
    float* hout = routed ? g_h : g_hs;

    __shared__ float As[BK][BM];
    __shared__ float B1s[BK][BN];
    __shared__ float B3s[BK][BN];
    __shared__ int rowSlot[BM];
    __shared__ int rowTok[BM];

    int tid = threadIdx.x;
    if (tid < BM) {
        int r = row0 + tid;
        int slot = -1;
        if (r < M) slot = routed ? lst[r] : r;
        rowSlot[tid] = slot;
        rowTok[tid] = (slot >= 0) ? (routed ? (slot >> 1) : slot) : 0;
    }
    __syncthreads();

    float acc1[4][4] = {};
    float acc3[4][4] = {};
    int tx = tid & 15, ty = tid >> 4;

    int ar = tid >> 2;          // 0..63  (A row)
    int ak = (tid & 3) * 4;     // k sub-offset
    int br = tid >> 4;          // 0..15  (B k-row)
    int bn = (tid & 15) * 4;    // B col

    for (int k0 = 0; k0 < DIMSZ; k0 += BK) {
        {
            int tok = rowTok[ar];
            float4 v = *(const float4*)(x + (size_t)tok * DIMSZ + k0 + ak);
            As[ak + 0][ar] = v.x; As[ak + 1][ar] = v.y;
            As[ak + 2][ar] = v.z; As[ak + 3][ar] = v.w;
        }
        {
            float4 v1 = *(const float4*)(W1 + (size_t)(k0 + br) * HIDSZ + col0 + bn);
            *(float4*)&B1s[br][bn] = v1;
            float4 v3 = *(const float4*)(W3 + (size_t)(k0 + br) * HIDSZ + col0 + bn);
            *(float4*)&B3s[br][bn] = v3;
        }
        __syncthreads();
#pragma unroll
        for (int k = 0; k < BK; k++) {
            float4 av = *(float4*)&As[k][ty * 4];
            float4 b1 = *(float4*)&B1s[k][tx * 4];
            float4 b3 = *(float4*)&B3s[k][tx * 4];
            float a[4] = {av.x, av.y, av.z, av.w};
            float c1[4] = {b1.x, b1.y, b1.z, b1.w};
            float c3[4] = {b3.x, b3.y, b3.z, b3.w};
#pragma unroll
            for (int i = 0; i < 4; i++) {
#pragma unroll
                for (int j = 0; j < 4; j++) {
                    acc1[i][j] += a[i] * c1[j];
                    acc3[i][j] += a[i] * c3[j];
                }
            }
        }
        __syncthreads();
    }

    // epilogue: silu(acc1) * acc3
#pragma unroll
    for (int i = 0; i < 4; i++) {
        int slot = rowSlot[ty * 4 + i];
        if (slot < 0) continue;
        float* hrow = hout + (size_t)slot * HIDSZ + col0 + tx * 4;
        float4 o;
        float v;
        v = acc1[i][0]; o.x = (v / (1.f + expf(-v))) * acc3[i][0];
        v = acc1[i][1]; o.y = (v / (1.f + expf(-v))) * acc3[i][1];
        v = acc1[i][2]; o.z = (v / (1.f + expf(-v))) * acc3[i][2];
        v = acc1[i][3]; o.w = (v / (1.f + expf(-v))) * acc3[i][3];
        *(float4*)hrow = o;
    }
}

// ---------------- down projection: y = scale * (h @ W2) ----------------
// routed=1: A rows = g_h[slot], out -> g_ys[slot], scale = g_p[slot]
// routed=0: A rows = g_hs[token], out -> d_out[token], scale = 1
__global__ __launch_bounds__(256) void ffn_down_kernel(const float* __restrict__ w2,
                                                       float* __restrict__ out,
                                                       int routed) {
    int e = blockIdx.z;
    int M;
    const int* lst = nullptr;
    if (routed) { M = g_count[e]; lst = g_list[e]; }
    else M = T_TOK;
    int row0 = blockIdx.x * BM;
    if (row0 >= M) return;
    const float* W2 = w2 + (size_t)e * HIDSZ * DIMSZ;
    int col0 = blockIdx.y * BN;
    const float* hin = routed ? g_h : g_hs;
    float* yout = routed ? g_ys : out;

    __shared__ float As[BK][BM];
    __shared__ float Bs[BK][BN];
    __shared__ int rowSlot[BM];

    int tid = threadIdx.x;
    if (tid < BM) {
        int r = row0 + tid;
        int slot = -1;
        if (r < M) slot = routed ? lst[r] : r;
        rowSlot[tid] = slot;
    }
    __syncthreads();

    float acc[4][4] = {};
    int tx = tid & 15, ty = tid >> 4;

    int ar = tid >> 2;
    int ak = (tid & 3) * 4;
    int br = tid >> 4;
    int bn = (tid & 15) * 4;

    for (int k0 = 0; k0 < HIDSZ; k0 += BK) {
        {
            int slot = rowSlot[ar];
            int arow = (slot >= 0) ? slot : 0;
            float4 v = *(const float4*)(hin + (size_t)arow * HIDSZ + k0 + ak);
            As[ak + 0][ar] = v.x; As[ak + 1][ar] = v.y;
            As[ak + 2][ar] = v.z; As[ak + 3][ar] = v.w;
        }
        {
            float4 v = *(const float4*)(W2 + (size_t)(k0 + br) * DIMSZ + col0 + bn);
            *(float4*)&Bs[br][bn] = v;
        }
        __syncthreads();
#pragma unroll
        for (int k = 0; k < BK; k++) {
            float4 av = *(float4*)&As[k][ty * 4];
            float4 bv = *(float4*)&Bs[k][tx * 4];
            float a[4] = {av.x, av.y, av.z, av.w};
            float bb[4] = {bv.x, bv.y, bv.z, bv.w};
#pragma unroll
            for (int i = 0; i < 4; i++) {
#pragma unroll
                for (int j = 0; j < 4; j++) acc[i][j] += a[i] * bb[j];
            }
        }
        __syncthreads();
    }

#pragma unroll
    for (int i = 0; i < 4; i++) {
        int slot = rowSlot[ty * 4 + i];
        if (slot < 0) continue;
        float scale = routed ? g_p[slot] : 1.f;
        float* yrow = yout + (size_t)slot * DIMSZ + col0 + tx * 4;
        float4 o;
        o.x = scale * acc[i][0];
        o.y = scale * acc[i][1];
        o.z = scale * acc[i][2];
        o.w = scale * acc[i][3];
        *(float4*)yrow = o;
    }
}

// ---------------- combine: out[t] += ys[2t] + ys[2t+1] ----------------
__global__ void combine_kernel(float* __restrict__ out) {
    int idx = blockIdx.x * blockDim.x + threadIdx.x;      // over T*D/4
    const int n4 = T_TOK * DIMSZ / 4;
    if (idx >= n4) return;
    int dim4 = DIMSZ / 4;
    int t = idx / dim4;
    int d = idx % dim4;
    float4 o  = ((float4*)out)[idx];
    float4 y0 = ((const float4*)g_ys)[(size_t)(2 * t) * dim4 + d];
    float4 y1 = ((const float4*)g_ys)[(size_t)(2 * t + 1) * dim4 + d];
    o.x += y0.x + y1.x;
    o.y += y0.y + y1.y;
    o.z += y0.z + y1.z;
    o.w += y0.w + y1.w;
    ((float4*)out)[idx] = o;
}

// ---------------- launcher ----------------
extern "C" void kernel_launch(void* const* d_in, const int* in_sizes, int n_in,
                              void* d_out, int out_size) {
    const float* x      = (const float*)d_in[0];
    const float* gate_w = (const float*)d_in[1];
    const float* biases = (const float*)d_in[2];
    const float* w1     = (const float*)d_in[3];
    const float* w3     = (const float*)d_in[4];
    const float* w2     = (const float*)d_in[5];
    const float* sw1    = (const float*)d_in[6];
    const float* sw3    = (const float*)d_in[7];
    const float* sw2    = (const float*)d_in[8];
    float* out          = (float*)d_out;

    reset_counts_kernel<<<1, 32>>>();
    router_kernel<<<T_TOK / 8, 256>>>(x, gate_w, biases);

    // shared expert
    ffn_up_kernel<<<dim3(T_TOK / BM, HIDSZ / BN, 1), 256>>>(x, sw1, sw3, 0);
    ffn_down_kernel<<<dim3(T_TOK / BM, DIMSZ / BN, 1), 256>>>(sw2, out, 0);

    // routed experts (grouped gather GEMMs; empty tiles exit early)
    ffn_up_kernel<<<dim3(T_TOK / BM, HIDSZ / BN, NE), 256>>>(x, w1, w3, 1);
    ffn_down_kernel<<<dim3(T_TOK / BM, DIMSZ / BN, NE), 256>>>(w2, out, 1);

    combine_kernel<<<(T_TOK * DIMSZ / 4 + 255) / 256, 256>>>(out);
}

// round 2
// speedup vs baseline: 2.7340x; 2.7340x over previous
#include <cuda_runtime.h>
#include <math.h>

// Problem constants
#define T_TOK 8192
#define DIMSZ 512
#define HIDSZ 1024
#define NE    8
#define TOPK  2

// ---------------- device scratch ----------------
__device__ int   g_count[NE];
__device__ int   g_list[NE][T_TOK];
__device__ float g_p[T_TOK * TOPK];
__device__ float g_h[(size_t)T_TOK * TOPK * HIDSZ];
__device__ float g_hs[(size_t)T_TOK * HIDSZ];
__device__ float g_ys[(size_t)T_TOK * TOPK * DIMSZ];

__device__ __forceinline__ float cvt_tf32(float v) {
    unsigned u;
    asm("cvt.rna.tf32.f32 %0, %1;" : "=r"(u) : "f"(v));
    return __uint_as_float(u);
}

#define MMA_TF32(C, A, B0, B1)                                                  \
    asm volatile(                                                               \
        "mma.sync.aligned.m16n8k8.row.col.f32.tf32.tf32.f32 "                   \
        "{%0,%1,%2,%3}, {%4,%5,%6,%7}, {%8,%9}, {%0,%1,%2,%3};"                 \
        : "+f"((C)[0]), "+f"((C)[1]), "+f"((C)[2]), "+f"((C)[3])                 \
        : "r"((A)[0]), "r"((A)[1]), "r"((A)[2]), "r"((A)[3]), "r"(B0), "r"(B1))

// ---------------- reset ----------------
__global__ void reset_counts_kernel() {
    if (threadIdx.x < NE) g_count[threadIdx.x] = 0;
}

// ---------------- router ----------------
__global__ void router_kernel(const float* __restrict__ x,
                              const float* __restrict__ gw,
                              const float* __restrict__ biases) {
    int warp = (blockIdx.x * blockDim.x + threadIdx.x) >> 5;
    int lane = threadIdx.x & 31;
    if (warp >= T_TOK) return;
    const float* xt = x + (size_t)warp * DIMSZ;

    float sc[NE];
#pragma unroll
    for (int e = 0; e < NE; e++) sc[e] = 0.f;
    for (int i = lane; i < DIMSZ; i += 32) {
        float xv = xt[i];
#pragma unroll
        for (int e = 0; e < NE; e++) sc[e] += xv * gw[e * DIMSZ + i];
    }
#pragma unroll
    for (int e = 0; e < NE; e++) {
#pragma unroll
        for (int off = 16; off; off >>= 1)
            sc[e] += __shfl_xor_sync(0xffffffffu, sc[e], off);
    }
    if (lane != 0) return;

    float b[NE];
#pragma unroll
    for (int e = 0; e < NE; e++) b[e] = sc[e] + biases[e];
    int i0 = 0;
#pragma unroll
    for (int e = 1; e < NE; e++) if (b[e] > b[i0]) i0 = e;
    int i1 = (i0 == 0) ? 1 : 0;
#pragma unroll
    for (int e = 0; e < NE; e++) if (e != i0 && b[e] > b[i1]) i1 = e;

    int a0 = 0;
#pragma unroll
    for (int e = 1; e < NE; e++) if (sc[e] > sc[a0]) a0 = e;
    int a1 = (a0 == 0) ? 1 : 0;
#pragma unroll
    for (int e = 0; e < NE; e++) if (e != a0 && sc[e] > sc[a1]) a1 = e;

    float p0 = 1.f / (1.f + expf(-sc[a0]));
    float p1 = 1.f / (1.f + expf(-sc[a1]));
    float s = p0 + p1;
    p0 /= s; p1 /= s;

    int t = warp;
    int pos0 = atomicAdd(&g_count[i0], 1);
    g_list[i0][pos0] = t * 2 + 0;
    g_p[t * 2 + 0] = p0;
    int pos1 = atomicAdd(&g_count[i1], 1);
    g_list[i1][pos1] = t * 2 + 1;
    g_p[t * 2 + 1] = p1;
}

// ================= up projection (tensor core, tf32) =================
// CTA tile 128x64x32, 8 warps (4x2), warp tile 32x32, dual-B (w1 & w3)
__global__ __launch_bounds__(256, 2) void ffn_up_tc(const float* __restrict__ x,
                                                    const float* __restrict__ w1,
                                                    const float* __restrict__ w3,
                                                    int routed) {
    int e = blockIdx.z;
    int M = routed ? g_count[e] : T_TOK;
    int row0 = blockIdx.x * 128;
    if (row0 >= M) return;
    const float* W1 = w1 + (size_t)(routed ? e : 0) * DIMSZ * HIDSZ;
    const float* W3 = w3 + (size_t)(routed ? e : 0) * DIMSZ * HIDSZ;
    int col0 = blockIdx.y * 64;
    float* hout = routed ? g_h : g_hs;

    __shared__ float As[128][36];    // stride 36 -> conflict-free frag reads
    __shared__ float B1s[32][72];    // stride 72 (== 8 mod 32)
    __shared__ float B3s[32][72];
    __shared__ int sSlot[128];
    __shared__ int sTok[128];

    int tid = threadIdx.x;
    if (tid < 128) {
        int r = row0 + tid;
        int slot = (r < M) ? (routed ? g_list[e][r] : r) : -1;
        sSlot[tid] = slot;
        sTok[tid] = (slot < 0) ? 0 : (routed ? (slot >> 1) : slot);
    }
    __syncthreads();

    int warp = tid >> 5, lane = tid & 31;
    int gid = lane >> 2, tig = lane & 3;
    int wm = warp >> 1, wc = warp & 1;

    float acc1[2][4][4] = {};
    float acc3[2][4][4] = {};

    for (int k0 = 0; k0 < DIMSZ; k0 += 32) {
        // A: 128x32 -> 1024 float4, 4 per thread
#pragma unroll
        for (int j = 0; j < 4; j++) {
            int i = tid + j * 256;
            int row = i >> 3, c4 = (i & 7) * 4;
            int tok = sTok[row];
            float4 v = *(const float4*)(x + (size_t)tok * DIMSZ + k0 + c4);
            float4 w;
            w.x = cvt_tf32(v.x); w.y = cvt_tf32(v.y);
            w.z = cvt_tf32(v.z); w.w = cvt_tf32(v.w);
            *(float4*)&As[row][c4] = w;
        }
        // B1,B3: 32x64 each -> 512 float4 each, 2+2 per thread
#pragma unroll
        for (int j = 0; j < 2; j++) {
            int i = tid + j * 256;
            int kr = i >> 4, c4 = (i & 15) * 4;
            float4 v = *(const float4*)(W1 + (size_t)(k0 + kr) * HIDSZ + col0 + c4);
            float4 w;
            w.x = cvt_tf32(v.x); w.y = cvt_tf32(v.y);
            w.z = cvt_tf32(v.z); w.w = cvt_tf32(v.w);
            *(float4*)&B1s[kr][c4] = w;
            float4 u = *(const float4*)(W3 + (size_t)(k0 + kr) * HIDSZ + col0 + c4);
            float4 z;
            z.x = cvt_tf32(u.x); z.y = cvt_tf32(u.y);
            z.z = cvt_tf32(u.z); z.w = cvt_tf32(u.w);
            *(float4*)&B3s[kr][c4] = z;
        }
        __syncthreads();

#pragma unroll
        for (int kk = 0; kk < 32; kk += 8) {
            unsigned a[2][4];
#pragma unroll
            for (int ma = 0; ma < 2; ma++) {
                int rb = wm * 32 + ma * 16 + gid;
                a[ma][0] = __float_as_uint(As[rb][kk + tig]);
                a[ma][1] = __float_as_uint(As[rb + 8][kk + tig]);
                a[ma][2] = __float_as_uint(As[rb][kk + tig + 4]);
                a[ma][3] = __float_as_uint(As[rb + 8][kk + tig + 4]);
            }
#pragma unroll
            for (int na = 0; na < 4; na++) {
                int c = wc * 32 + na * 8 + gid;
                unsigned b0 = __float_as_uint(B1s[kk + tig][c]);
                unsigned b1 = __float_as_uint(B1s[kk + tig + 4][c]);
                unsigned d0 = __float_as_uint(B3s[kk + tig][c]);
                unsigned d1 = __float_as_uint(B3s[kk + tig + 4][c]);
#pragma unroll
                for (int ma = 0; ma < 2; ma++) {
                    MMA_TF32(acc1[ma][na], a[ma], b0, b1);
                    MMA_TF32(acc3[ma][na], a[ma], d0, d1);
                }
            }
        }
        __syncthreads();
    }

    // epilogue: silu(acc1)*acc3
#pragma unroll
    for (int ma = 0; ma < 2; ma++) {
#pragma unroll
        for (int rs = 0; rs < 2; rs++) {
            int row = wm * 32 + ma * 16 + rs * 8 + gid;
            int slot = sSlot[row];
            if (slot < 0) continue;
            float* hp = hout + (size_t)slot * HIDSZ + col0 + wc * 32;
#pragma unroll
            for (int na = 0; na < 4; na++) {
                float s0 = acc1[ma][na][rs * 2 + 0];
                float s1 = acc1[ma][na][rs * 2 + 1];
                float t0 = acc3[ma][na][rs * 2 + 0];
                float t1 = acc3[ma][na][rs * 2 + 1];
                float2 o;
                o.x = (s0 / (1.f + expf(-s0))) * t0;
                o.y = (s1 / (1.f + expf(-s1))) * t1;
                *(float2*)(hp + na * 8 + tig * 2) = o;
            }
        }
    }
}

// ================= down projection (tensor core, tf32) =================
// CTA tile 128x128x32, 8 warps (2x4), warp tile 64x32
__global__ __launch_bounds__(256, 2) void ffn_down_tc(const float* __restrict__ w2,
                                                      float* __restrict__ out,
                                                      int routed) {
    int e = blockIdx.z;
    int M = routed ? g_count[e] : T_TOK;
    int row0 = blockIdx.x * 128;
    if (row0 >= M) return;
    const float* W2 = w2 + (size_t)(routed ? e : 0) * HIDSZ * DIMSZ;
    int col0 = blockIdx.y * 128;
    const float* hin = routed ? g_h : g_hs;

    __shared__ float As[128][36];
    __shared__ float Bs[32][136];    // stride 136 (== 8 mod 32)
    __shared__ int sSlot[128];

    int tid = threadIdx.x;
    if (tid < 128) {
        int r = row0 + tid;
        sSlot[tid] = (r < M) ? (routed ? g_list[e][r] : r) : -1;
    }
    __syncthreads();

    int warp = tid >> 5, lane = tid & 31;
    int gid = lane >> 2, tig = lane & 3;
    int wm = warp >> 2, wc = warp & 3;

    float acc[4][4][4] = {};

    for (int k0 = 0; k0 < HIDSZ; k0 += 32) {
        // A: 128x32 = 1024 float4, 4/thread
#pragma unroll
        for (int j = 0; j < 4; j++) {
            int i = tid + j * 256;
            int row = i >> 3, c4 = (i & 7) * 4;
            int slot = sSlot[row];
            int ar = (slot < 0) ? 0 : slot;
            float4 v = *(const float4*)(hin + (size_t)ar * HIDSZ + k0 + c4);
            float4 w;
            w.x = cvt_tf32(v.x); w.y = cvt_tf32(v.y);
            w.z = cvt_tf32(v.z); w.w = cvt_tf32(v.w);
            *(float4*)&As[row][c4] = w;
        }
        // B: 32x128 = 1024 float4, 4/thread
#pragma unroll
        for (int j = 0; j < 4; j++) {
            int i = tid + j * 256;
            int kr = i >> 5, c4 = (i & 31) * 4;
            float4 v = *(const float4*)(W2 + (size_t)(k0 + kr) * DIMSZ + col0 + c4);
            float4 w;
            w.x = cvt_tf32(v.x); w.y = cvt_tf32(v.y);
            w.z = cvt_tf32(v.z); w.w = cvt_tf32(v.w);
            *(float4*)&Bs[kr][c4] = w;
        }
        __syncthreads();

#pragma unroll
        for (int kk = 0; kk < 32; kk += 8) {
            unsigned a[4][4];
#pragma unroll
            for (int ma = 0; ma < 4; ma++) {
                int rb = wm * 64 + ma * 16 + gid;
                a[ma][0] = __float_as_uint(As[rb][kk + tig]);
                a[ma][1] = __float_as_uint(As[rb + 8][kk + tig]);
                a[ma][2] = __float_as_uint(As[rb][kk + tig + 4]);
                a[ma][3] = __float_as_uint(As[rb + 8][kk + tig + 4]);
            }
#pragma unroll
            for (int na = 0; na < 4; na++) {
                int c = wc * 32 + na * 8 + gid;
                unsigned b0 = __float_as_uint(Bs[kk + tig][c]);
                unsigned b1 = __float_as_uint(Bs[kk + tig + 4][c]);
#pragma unroll
                for (int ma = 0; ma < 4; ma++) {
                    MMA_TF32(acc[ma][na], a[ma], b0, b1);
                }
            }
        }
        __syncthreads();
    }

#pragma unroll
    for (int ma = 0; ma < 4; ma++) {
#pragma unroll
        for (int rs = 0; rs < 2; rs++) {
            int row = wm * 64 + ma * 16 + rs * 8 + gid;
            int slot = sSlot[row];
            if (slot < 0) continue;
            float scale = routed ? g_p[slot] : 1.f;
            float* yp = (routed ? g_ys : out) + (size_t)slot * DIMSZ + col0 + wc * 32;
#pragma unroll
            for (int na = 0; na < 4; na++) {
                float2 o;
                o.x = scale * acc[ma][na][rs * 2 + 0];
                o.y = scale * acc[ma][na][rs * 2 + 1];
                *(float2*)(yp + na * 8 + tig * 2) = o;
            }
        }
    }
}

// ---------------- combine ----------------
__global__ void combine_kernel(float* __restrict__ out) {
    int idx = blockIdx.x * blockDim.x + threadIdx.x;
    const int n4 = T_TOK * DIMSZ / 4;
    if (idx >= n4) return;
    int dim4 = DIMSZ / 4;
    int t = idx / dim4;
    int d = idx % dim4;
    float4 o  = ((float4*)out)[idx];
    float4 y0 = ((const float4*)g_ys)[(size_t)(2 * t) * dim4 + d];
    float4 y1 = ((const float4*)g_ys)[(size_t)(2 * t + 1) * dim4 + d];
    o.x += y0.x + y1.x;
    o.y += y0.y + y1.y;
    o.z += y0.z + y1.z;
    o.w += y0.w + y1.w;
    ((float4*)out)[idx] = o;
}

// ---------------- launcher ----------------
extern "C" void kernel_launch(void* const* d_in, const int* in_sizes, int n_in,
                              void* d_out, int out_size) {
    const float* x      = (const float*)d_in[0];
    const float* gate_w = (const float*)d_in[1];
    const float* biases = (const float*)d_in[2];
    const float* w1     = (const float*)d_in[3];
    const float* w3     = (const float*)d_in[4];
    const float* w2     = (const float*)d_in[5];
    const float* sw1    = (const float*)d_in[6];
    const float* sw3    = (const float*)d_in[7];
    const float* sw2    = (const float*)d_in[8];
    float* out          = (float*)d_out;

    reset_counts_kernel<<<1, 32>>>();
    router_kernel<<<T_TOK / 8, 256>>>(x, gate_w, biases);

    // shared expert
    ffn_up_tc<<<dim3(T_TOK / 128, HIDSZ / 64, 1), 256>>>(x, sw1, sw3, 0);
    ffn_down_tc<<<dim3(T_TOK / 128, DIMSZ / 128, 1), 256>>>(sw2, out, 0);

    // routed experts
    ffn_up_tc<<<dim3(T_TOK / 128, HIDSZ / 64, NE), 256>>>(x, w1, w3, 1);
    ffn_down_tc<<<dim3(T_TOK / 128, DIMSZ / 128, NE), 256>>>(w2, out, 1);

    combine_kernel<<<(T_TOK * DIMSZ / 4 + 255) / 256, 256>>>(out);
}

// round 3
// speedup vs baseline: 3.8404x; 1.4047x over previous
#include <cuda_runtime.h>
#include <math.h>
#include <stdint.h>

// Problem constants
#define T_TOK 8192
#define DIMSZ 512
#define HIDSZ 1024
#define NE    8
#define TOPK  2

// ---------------- device scratch ----------------
__device__ int   g_count[NE];
__device__ int   g_list[NE][T_TOK];
__device__ float g_p[T_TOK * TOPK];
__device__ float g_h[(size_t)T_TOK * TOPK * HIDSZ];    // tf32-rounded
__device__ float g_hs[(size_t)T_TOK * HIDSZ];          // tf32-rounded
__device__ float g_ys[(size_t)T_TOK * TOPK * DIMSZ];

// tf32 pre-converted operands
__device__ float g_xc[(size_t)T_TOK * DIMSZ];
__device__ float g_w1c[(size_t)NE * DIMSZ * HIDSZ];
__device__ float g_w3c[(size_t)NE * DIMSZ * HIDSZ];
__device__ float g_w2c[(size_t)NE * HIDSZ * DIMSZ];
__device__ float g_sw1c[(size_t)DIMSZ * HIDSZ];
__device__ float g_sw3c[(size_t)DIMSZ * HIDSZ];
__device__ float g_sw2c[(size_t)HIDSZ * DIMSZ];

__device__ __forceinline__ float cvt_tf32(float v) {
    unsigned u;
    asm("cvt.rna.tf32.f32 %0, %1;" : "=r"(u) : "f"(v));
    return __uint_as_float(u);
}

#define MMA_TF32(C, A, B0, B1)                                                  \
    asm volatile(                                                               \
        "mma.sync.aligned.m16n8k8.row.col.f32.tf32.tf32.f32 "                   \
        "{%0,%1,%2,%3}, {%4,%5,%6,%7}, {%8,%9}, {%0,%1,%2,%3};"                 \
        : "+f"((C)[0]), "+f"((C)[1]), "+f"((C)[2]), "+f"((C)[3])                 \
        : "r"((A)[0]), "r"((A)[1]), "r"((A)[2]), "r"((A)[3]), "r"(B0), "r"(B1))

__device__ __forceinline__ void cp_async16(void* sptr, const void* gptr) {
    uint32_t sa = (uint32_t)__cvta_generic_to_shared(sptr);
    asm volatile("cp.async.cg.shared.global [%0], [%1], 16;" :: "r"(sa), "l"(gptr));
}
#define CP_COMMIT()  asm volatile("cp.async.commit_group;")
#define CP_WAIT(N)   asm volatile("cp.async.wait_group %0;" :: "n"(N))

// ---------------- converters ----------------
__global__ void cvt_kernel(const float* __restrict__ in, float* __restrict__ out, int n4) {
    int i = blockIdx.x * blockDim.x + threadIdx.x;
    if (i >= n4) return;
    float4 v = ((const float4*)in)[i];
    float4 w;
    w.x = cvt_tf32(v.x); w.y = cvt_tf32(v.y);
    w.z = cvt_tf32(v.z); w.w = cvt_tf32(v.w);
    ((float4*)out)[i] = w;
}

// ---------------- reset ----------------
__global__ void reset_counts_kernel() {
    if (threadIdx.x < NE) g_count[threadIdx.x] = 0;
}

// ---------------- router ----------------
__global__ void router_kernel(const float* __restrict__ x,
                              const float* __restrict__ gw,
                              const float* __restrict__ biases) {
    int warp = (blockIdx.x * blockDim.x + threadIdx.x) >> 5;
    int lane = threadIdx.x & 31;
    if (warp >= T_TOK) return;
    const float* xt = x + (size_t)warp * DIMSZ;

    float sc[NE];
#pragma unroll
    for (int e = 0; e < NE; e++) sc[e] = 0.f;
    for (int i = lane; i < DIMSZ; i += 32) {
        float xv = xt[i];
#pragma unroll
        for (int e = 0; e < NE; e++) sc[e] += xv * gw[e * DIMSZ + i];
    }
#pragma unroll
    for (int e = 0; e < NE; e++) {
#pragma unroll
        for (int off = 16; off; off >>= 1)
            sc[e] += __shfl_xor_sync(0xffffffffu, sc[e], off);
    }
    if (lane != 0) return;

    float b[NE];
#pragma unroll
    for (int e = 0; e < NE; e++) b[e] = sc[e] + biases[e];
    int i0 = 0;
#pragma unroll
    for (int e = 1; e < NE; e++) if (b[e] > b[i0]) i0 = e;
    int i1 = (i0 == 0) ? 1 : 0;
#pragma unroll
    for (int e = 0; e < NE; e++) if (e != i0 && b[e] > b[i1]) i1 = e;

    int a0 = 0;
#pragma unroll
    for (int e = 1; e < NE; e++) if (sc[e] > sc[a0]) a0 = e;
    int a1 = (a0 == 0) ? 1 : 0;
#pragma unroll
    for (int e = 0; e < NE; e++) if (e != a0 && sc[e] > sc[a1]) a1 = e;

    float p0 = 1.f / (1.f + expf(-sc[a0]));
    float p1 = 1.f / (1.f + expf(-sc[a1]));
    float s = p0 + p1;
    p0 /= s; p1 /= s;

    int t = warp;
    int pos0 = atomicAdd(&g_count[i0], 1);
    g_list[i0][pos0] = t * 2 + 0;
    g_p[t * 2 + 0] = p0;
    int pos1 = atomicAdd(&g_count[i1], 1);
    g_list[i1][pos1] = t * 2 + 1;
    g_p[t * 2 + 1] = p1;
}

// ================= up projection (tf32 mma + cp.async double buffer) =================
// CTA 128x64x32, 8 warps (4x2), warp tile 32x32, dual-B
#define UP_A_ST   (128 * 36)
#define UP_B_ST   (32 * 72)
__global__ __launch_bounds__(256, 2) void ffn_up_tc(const float* __restrict__ w1,
                                                    const float* __restrict__ w3,
                                                    int routed) {
    extern __shared__ float smem[];
    float* sA  = smem;                     // [2][128][36]
    float* sB1 = sA + 2 * UP_A_ST;         // [2][32][72]
    float* sB3 = sB1 + 2 * UP_B_ST;        // [2][32][72]
    __shared__ int sSlot[128];
    __shared__ int sTok[128];

    int e = blockIdx.z;
    int M = routed ? g_count[e] : T_TOK;
    int row0 = blockIdx.x * 128;
    if (row0 >= M) return;
    const float* W1 = w1 + (size_t)(routed ? e : 0) * DIMSZ * HIDSZ;
    const float* W3 = w3 + (size_t)(routed ? e : 0) * DIMSZ * HIDSZ;
    int col0 = blockIdx.y * 64;
    float* hout = routed ? g_h : g_hs;

    int tid = threadIdx.x;
    if (tid < 128) {
        int r = row0 + tid;
        int slot = (r < M) ? (routed ? g_list[e][r] : r) : -1;
        sSlot[tid] = slot;
        sTok[tid] = (slot < 0) ? 0 : (routed ? (slot >> 1) : slot);
    }
    __syncthreads();

    int warp = tid >> 5, lane = tid & 31;
    int gid = lane >> 2, tig = lane & 3;
    int wm = warp >> 1, wc = warp & 1;

    // load thread mapping
    int a_row = tid >> 3, a_c4 = (tid & 7) * 4;        // + j*32 rows
    int b_kr = tid >> 4, b_c4 = (tid & 15) * 4;        // + j*16 rows

    float acc1[2][4][4] = {};
    float acc3[2][4][4] = {};

    const int nIter = DIMSZ / 32;

    // stage-load lambda (macro style)
#define UP_LOAD(ST, K0)                                                          \
    {                                                                            \
        _Pragma("unroll")                                                        \
        for (int j = 0; j < 4; j++) {                                            \
            int row = a_row + j * 32;                                            \
            int tok = sTok[row];                                                 \
            cp_async16(&sA[(ST) * UP_A_ST + row * 36 + a_c4],                    \
                       g_xc + (size_t)tok * DIMSZ + (K0) + a_c4);                \
        }                                                                        \
        _Pragma("unroll")                                                        \
        for (int j = 0; j < 2; j++) {                                            \
            int kr = b_kr + j * 16;                                              \
            cp_async16(&sB1[(ST) * UP_B_ST + kr * 72 + b_c4],                    \
                       W1 + (size_t)((K0) + kr) * HIDSZ + col0 + b_c4);          \
            cp_async16(&sB3[(ST) * UP_B_ST + kr * 72 + b_c4],                    \
                       W3 + (size_t)((K0) + kr) * HIDSZ + col0 + b_c4);          \
        }                                                                        \
    }

    UP_LOAD(0, 0);
    CP_COMMIT();

    for (int it = 0; it < nIter; it++) {
        int cur = it & 1;
        if (it + 1 < nIter) {
            UP_LOAD((it + 1) & 1, (it + 1) * 32);
            CP_COMMIT();
            CP_WAIT(1);
        } else {
            CP_WAIT(0);
        }
        __syncthreads();

        const float* As = sA + cur * UP_A_ST;
        const float* B1s = sB1 + cur * UP_B_ST;
        const float* B3s = sB3 + cur * UP_B_ST;
#pragma unroll
        for (int kk = 0; kk < 32; kk += 8) {
            unsigned a[2][4];
#pragma unroll
            for (int ma = 0; ma < 2; ma++) {
                int rb = wm * 32 + ma * 16 + gid;
                a[ma][0] = __float_as_uint(As[rb * 36 + kk + tig]);
                a[ma][1] = __float_as_uint(As[(rb + 8) * 36 + kk + tig]);
                a[ma][2] = __float_as_uint(As[rb * 36 + kk + tig + 4]);
                a[ma][3] = __float_as_uint(As[(rb + 8) * 36 + kk + tig + 4]);
            }
#pragma unroll
            for (int na = 0; na < 4; na++) {
                int c = wc * 32 + na * 8 + gid;
                unsigned b0 = __float_as_uint(B1s[(kk + tig) * 72 + c]);
                unsigned b1 = __float_as_uint(B1s[(kk + tig + 4) * 72 + c]);
                unsigned d0 = __float_as_uint(B3s[(kk + tig) * 72 + c]);
                unsigned d1 = __float_as_uint(B3s[(kk + tig + 4) * 72 + c]);
#pragma unroll
                for (int ma = 0; ma < 2; ma++) {
                    MMA_TF32(acc1[ma][na], a[ma], b0, b1);
                    MMA_TF32(acc3[ma][na], a[ma], d0, d1);
                }
            }
        }
        __syncthreads();
    }

    // epilogue: silu(acc1)*acc3, store tf32-rounded for the down GEMM
#pragma unroll
    for (int ma = 0; ma < 2; ma++) {
#pragma unroll
        for (int rs = 0; rs < 2; rs++) {
            int row = wm * 32 + ma * 16 + rs * 8 + gid;
            int slot = sSlot[row];
            if (slot < 0) continue;
            float* hp = hout + (size_t)slot * HIDSZ + col0 + wc * 32;
#pragma unroll
            for (int na = 0; na < 4; na++) {
                float s0 = acc1[ma][na][rs * 2 + 0];
                float s1 = acc1[ma][na][rs * 2 + 1];
                float t0 = acc3[ma][na][rs * 2 + 0];
                float t1 = acc3[ma][na][rs * 2 + 1];
                float2 o;
                o.x = cvt_tf32((s0 / (1.f + expf(-s0))) * t0);
                o.y = cvt_tf32((s1 / (1.f + expf(-s1))) * t1);
                *(float2*)(hp + na * 8 + tig * 2) = o;
            }
        }
    }
}

// ================= down projection (tf32 mma + cp.async double buffer) =================
// CTA 128x128x32, 8 warps (2x4), warp tile 64x32
#define DN_A_ST   (128 * 36)
#define DN_B_ST   (32 * 136)
__global__ __launch_bounds__(256, 2) void ffn_down_tc(const float* __restrict__ w2,
                                                      float* __restrict__ out,
                                                      int routed) {
    extern __shared__ float smem[];
    float* sA = smem;                      // [2][128][36]
    float* sB = sA + 2 * DN_A_ST;          // [2][32][136]
    __shared__ int sSlot[128];

    int e = blockIdx.z;
    int M = routed ? g_count[e] : T_TOK;
    int row0 = blockIdx.x * 128;
    if (row0 >= M) return;
    const float* W2 = w2 + (size_t)(routed ? e : 0) * HIDSZ * DIMSZ;
    int col0 = blockIdx.y * 128;
    const float* hin = routed ? g_h : g_hs;

    int tid = threadIdx.x;
    if (tid < 128) {
        int r = row0 + tid;
        sSlot[tid] = (r < M) ? (routed ? g_list[e][r] : r) : -1;
    }
    __syncthreads();

    int warp = tid >> 5, lane = tid & 31;
    int gid = lane >> 2, tig = lane & 3;
    int wm = warp >> 2, wc = warp & 3;

    int a_row = tid >> 3, a_c4 = (tid & 7) * 4;
    int b_kr = tid >> 5, b_c4 = (tid & 31) * 4;

    float acc[4][4][4] = {};
    const int nIter = HIDSZ / 32;

#define DN_LOAD(ST, K0)                                                          \
    {                                                                            \
        _Pragma("unroll")                                                        \
        for (int j = 0; j < 4; j++) {                                            \
            int row = a_row + j * 32;                                            \
            int slot = sSlot[row];                                               \
            int ar = (slot < 0) ? 0 : slot;                                      \
            cp_async16(&sA[(ST) * DN_A_ST + row * 36 + a_c4],                    \
                       hin + (size_t)ar * HIDSZ + (K0) + a_c4);                  \
        }                                                                        \
        _Pragma("unroll")                                                        \
        for (int j = 0; j < 4; j++) {                                            \
            int kr = b_kr + j * 8;                                               \
            cp_async16(&sB[(ST) * DN_B_ST + kr * 136 + b_c4],                    \
                       W2 + (size_t)((K0) + kr) * DIMSZ + col0 + b_c4);          \
        }                                                                        \
    }

    DN_LOAD(0, 0);
    CP_COMMIT();

    for (int it = 0; it < nIter; it++) {
        int cur = it & 1;
        if (it + 1 < nIter) {
            DN_LOAD((it + 1) & 1, (it + 1) * 32);
            CP_COMMIT();
            CP_WAIT(1);
        } else {
            CP_WAIT(0);
        }
        __syncthreads();

        const float* As = sA + cur * DN_A_ST;
        const float* Bs = sB + cur * DN_B_ST;
#pragma unroll
        for (int kk = 0; kk < 32; kk += 8) {
            unsigned a[4][4];
#pragma unroll
            for (int ma = 0; ma < 4; ma++) {
                int rb = wm * 64 + ma * 16 + gid;
                a[ma][0] = __float_as_uint(As[rb * 36 + kk + tig]);
                a[ma][1] = __float_as_uint(As[(rb + 8) * 36 + kk + tig]);
                a[ma][2] = __float_as_uint(As[rb * 36 + kk + tig + 4]);
                a[ma][3] = __float_as_uint(As[(rb + 8) * 36 + kk + tig + 4]);
            }
#pragma unroll
            for (int na = 0; na < 4; na++) {
                int c = wc * 32 + na * 8 + gid;
                unsigned b0 = __float_as_uint(Bs[(kk + tig) * 136 + c]);
                unsigned b1 = __float_as_uint(Bs[(kk + tig + 4) * 136 + c]);
#pragma unroll
                for (int ma = 0; ma < 4; ma++) {
                    MMA_TF32(acc[ma][na], a[ma], b0, b1);
                }
            }
        }
        __syncthreads();
    }

#pragma unroll
    for (int ma = 0; ma < 4; ma++) {
#pragma unroll
        for (int rs = 0; rs < 2; rs++) {
            int row = wm * 64 + ma * 16 + rs * 8 + gid;
            int slot = sSlot[row];
            if (slot < 0) continue;
            float scale = routed ? g_p[slot] : 1.f;
            float* yp = (routed ? g_ys : out) + (size_t)slot * DIMSZ + col0 + wc * 32;
#pragma unroll
            for (int na = 0; na < 4; na++) {
                float2 o;
                o.x = scale * acc[ma][na][rs * 2 + 0];
                o.y = scale * acc[ma][na][rs * 2 + 1];
                *(float2*)(yp + na * 8 + tig * 2) = o;
            }
        }
    }
}

// ---------------- combine ----------------
__global__ void combine_kernel(float* __restrict__ out) {
    int idx = blockIdx.x * blockDim.x + threadIdx.x;
    const int n4 = T_TOK * DIMSZ / 4;
    if (idx >= n4) return;
    int dim4 = DIMSZ / 4;
    int t = idx / dim4;
    int d = idx % dim4;
    float4 o  = ((float4*)out)[idx];
    float4 y0 = ((const float4*)g_ys)[(size_t)(2 * t) * dim4 + d];
    float4 y1 = ((const float4*)g_ys)[(size_t)(2 * t + 1) * dim4 + d];
    o.x += y0.x + y1.x;
    o.y += y0.y + y1.y;
    o.z += y0.z + y1.z;
    o.w += y0.w + y1.w;
    ((float4*)out)[idx] = o;
}

// ---------------- launcher ----------------
extern "C" void kernel_launch(void* const* d_in, const int* in_sizes, int n_in,
                              void* d_out, int out_size) {
    const float* x      = (const float*)d_in[0];
    const float* gate_w = (const float*)d_in[1];
    const float* biases = (const float*)d_in[2];
    const float* w1     = (const float*)d_in[3];
    const float* w3     = (const float*)d_in[4];
    const float* w2     = (const float*)d_in[5];
    const float* sw1    = (const float*)d_in[6];
    const float* sw3    = (const float*)d_in[7];
    const float* sw2    = (const float*)d_in[8];
    float* out          = (float*)d_out;

    const int upSmem = (2 * UP_A_ST + 4 * UP_B_ST) * 4;   // ~ 73728 B
    const int dnSmem = (2 * DN_A_ST + 2 * DN_B_ST) * 4;   // ~ 71680 B
    cudaFuncSetAttribute(ffn_up_tc,  cudaFuncAttributeMaxDynamicSharedMemorySize, upSmem);
    cudaFuncSetAttribute(ffn_down_tc, cudaFuncAttributeMaxDynamicSharedMemorySize, dnSmem);

    // device pointers for scratch
    float *xc, *w1c, *w3c, *w2c, *sw1c, *sw3c, *sw2c;
    cudaGetSymbolAddress((void**)&xc,  g_xc);
    cudaGetSymbolAddress((void**)&w1c, g_w1c);
    cudaGetSymbolAddress((void**)&w3c, g_w3c);
    cudaGetSymbolAddress((void**)&w2c, g_w2c);
    cudaGetSymbolAddress((void**)&sw1c, g_sw1c);
    cudaGetSymbolAddress((void**)&sw3c, g_sw3c);
    cudaGetSymbolAddress((void**)&sw2c, g_sw2c);

    reset_counts_kernel<<<1, 32>>>();
    router_kernel<<<T_TOK / 8, 256>>>(x, gate_w, biases);

    // tf32 pre-conversion
    cvt_kernel<<<(T_TOK * DIMSZ / 4 + 255) / 256, 256>>>(x, xc, T_TOK * DIMSZ / 4);
    cvt_kernel<<<(NE * DIMSZ * HIDSZ / 4 + 255) / 256, 256>>>(w1, w1c, NE * DIMSZ * HIDSZ / 4);
    cvt_kernel<<<(NE * DIMSZ * HIDSZ / 4 + 255) / 256, 256>>>(w3, w3c, NE * DIMSZ * HIDSZ / 4);
    cvt_kernel<<<(NE * HIDSZ * DIMSZ / 4 + 255) / 256, 256>>>(w2, w2c, NE * HIDSZ * DIMSZ / 4);
    cvt_kernel<<<(DIMSZ * HIDSZ / 4 + 255) / 256, 256>>>(sw1, sw1c, DIMSZ * HIDSZ / 4);
    cvt_kernel<<<(DIMSZ * HIDSZ / 4 + 255) / 256, 256>>>(sw3, sw3c, DIMSZ * HIDSZ / 4);
    cvt_kernel<<<(HIDSZ * DIMSZ / 4 + 255) / 256, 256>>>(sw2, sw2c, HIDSZ * DIMSZ / 4);

    // shared expert
    ffn_up_tc<<<dim3(T_TOK / 128, HIDSZ / 64, 1), 256, upSmem>>>(sw1c, sw3c, 0);
    ffn_down_tc<<<dim3(T_TOK / 128, DIMSZ / 128, 1), 256, dnSmem>>>(sw2c, out, 0);

    // routed experts
    ffn_up_tc<<<dim3(T_TOK / 128, HIDSZ / 64, NE), 256, upSmem>>>(w1c, w3c, 1);
    ffn_down_tc<<<dim3(T_TOK / 128, DIMSZ / 128, NE), 256, dnSmem>>>(w2c, out, 1);

    combine_kernel<<<(T_TOK * DIMSZ / 4 + 255) / 256, 256>>>(out);
}

// round 8
// speedup vs baseline: 6.4137x; 1.6701x over previous
#include <cuda_runtime.h>
#include <cuda_fp16.h>
#include <math.h>
#include <stdint.h>

#define T_TOK 8192
#define DIMSZ 512
#define HIDSZ 1024
#define NE    8

// ---------------- device scratch ----------------
__device__ int    g_count[NE];
__device__ int    g_list[NE][T_TOK];
__device__ float  g_p[T_TOK * 2];
__device__ __half g_h[(size_t)T_TOK * 2 * HIDSZ];
__device__ __half g_hs[(size_t)T_TOK * HIDSZ];
__device__ float  g_ys[(size_t)T_TOK * 2 * DIMSZ];

__device__ __half g_xh[(size_t)T_TOK * DIMSZ];
__device__ __half g_w1t[(size_t)NE * HIDSZ * DIMSZ];   // [E][H][D]
__device__ __half g_w3t[(size_t)NE * HIDSZ * DIMSZ];
__device__ __half g_w2t[(size_t)NE * DIMSZ * HIDSZ];   // [E][D][H]
__device__ __half g_sw1t[(size_t)HIDSZ * DIMSZ];
__device__ __half g_sw3t[(size_t)HIDSZ * DIMSZ];
__device__ __half g_sw2t[(size_t)DIMSZ * HIDSZ];

// ---------------- helpers ----------------
__device__ __forceinline__ uint32_t smem_u32(const void* p) {
    uint32_t a;
    asm("{ .reg .u64 t; cvta.to.shared.u64 t, %1; cvt.u32.u64 %0, t; }" : "=r"(a) : "l"(p));
    return a;
}
__device__ __forceinline__ void cp16(uint32_t saddr, const void* g) {
    asm volatile("cp.async.cg.shared.global [%0], [%1], 16;" :: "r"(saddr), "l"(g));
}
#define CP_COMMIT()  asm volatile("cp.async.commit_group;")
#define CP_WAIT(N)   asm volatile("cp.async.wait_group %0;" :: "n"(N))

#define LDSM4(R, addr)                                                          \
    asm volatile("ldmatrix.sync.aligned.m8n8.x4.shared.b16 {%0,%1,%2,%3}, [%4];"\
        : "=r"((R)[0]), "=r"((R)[1]), "=r"((R)[2]), "=r"((R)[3]) : "r"(addr))

#define MMA16816(C, A, B0, B1)                                                  \
    asm volatile(                                                               \
        "mma.sync.aligned.m16n8k16.row.col.f32.f16.f16.f32 "                    \
        "{%0,%1,%2,%3}, {%4,%5,%6,%7}, {%8,%9}, {%0,%1,%2,%3};"                 \
        : "+f"((C)[0]), "+f"((C)[1]), "+f"((C)[2]), "+f"((C)[3])                 \
        : "r"((A)[0]), "r"((A)[1]), "r"((A)[2]), "r"((A)[3]), "r"(B0), "r"(B1))

__device__ __forceinline__ uint32_t swz(uint32_t off) {   // SW128 (Swizzle<3,4,3>)
    return off ^ ((off >> 3) & 0x70);
}

// ---------------- small kernels ----------------
__global__ void reset_counts_kernel() {
    if (threadIdx.x < NE) g_count[threadIdx.x] = 0;
}

__global__ void cvt_h_kernel(const float* __restrict__ in, __half* __restrict__ out, int n4) {
    int i = blockIdx.x * blockDim.x + threadIdx.x;
    if (i >= n4) return;
    float4 v = ((const float4*)in)[i];
    __half2* o = reinterpret_cast<__half2*>(out) + 2 * i;
    o[0] = __floats2half2_rn(v.x, v.y);
    o[1] = __floats2half2_rn(v.z, v.w);
}

// out[e][n][k] = half(in[e][k][n]); in: [E][K][N] fp32
__global__ void transpose_h_kernel(const float* __restrict__ in, __half* __restrict__ out,
                                   int K, int N) {
    __shared__ float tile[32][33];
    int e = blockIdx.z;
    const float* src = in + (size_t)e * K * N;
    __half* dst = out + (size_t)e * K * N;
    int n0 = blockIdx.x * 32, k0 = blockIdx.y * 32;
    for (int i = threadIdx.y; i < 32; i += 8)
        tile[i][threadIdx.x] = src[(size_t)(k0 + i) * N + n0 + threadIdx.x];
    __syncthreads();
    for (int i = threadIdx.y; i < 32; i += 8)
        dst[(size_t)(n0 + i) * K + k0 + threadIdx.x] = __float2half_rn(tile[threadIdx.x][i]);
}

__global__ void router_kernel(const float* __restrict__ x,
                              const float* __restrict__ gw,
                              const float* __restrict__ biases) {
    int warp = (blockIdx.x * blockDim.x + threadIdx.x) >> 5;
    int lane = threadIdx.x & 31;
    if (warp >= T_TOK) return;
    const float* xt = x + (size_t)warp * DIMSZ;

    float sc[NE];
#pragma unroll
    for (int e = 0; e < NE; e++) sc[e] = 0.f;
    for (int i = lane; i < DIMSZ; i += 32) {
        float xv = xt[i];
#pragma unroll
        for (int e = 0; e < NE; e++) sc[e] += xv * gw[e * DIMSZ + i];
    }
#pragma unroll
    for (int e = 0; e < NE; e++) {
#pragma unroll
        for (int off = 16; off; off >>= 1)
            sc[e] += __shfl_xor_sync(0xffffffffu, sc[e], off);
    }
    if (lane != 0) return;

    float b[NE];
#pragma unroll
    for (int e = 0; e < NE; e++) b[e] = sc[e] + biases[e];
    int i0 = 0;
#pragma unroll
    for (int e = 1; e < NE; e++) if (b[e] > b[i0]) i0 = e;
    int i1 = (i0 == 0) ? 1 : 0;
#pragma unroll
    for (int e = 0; e < NE; e++) if (e != i0 && b[e] > b[i1]) i1 = e;

    int a0 = 0;
#pragma unroll
    for (int e = 1; e < NE; e++) if (sc[e] > sc[a0]) a0 = e;
    int a1 = (a0 == 0) ? 1 : 0;
#pragma unroll
    for (int e = 0; e < NE; e++) if (e != a0 && sc[e] > sc[a1]) a1 = e;

    float p0 = 1.f / (1.f + expf(-sc[a0]));
    float p1 = 1.f / (1.f + expf(-sc[a1]));
    float s = p0 + p1;
    p0 /= s; p1 /= s;

    int t = warp;
    int pos0 = atomicAdd(&g_count[i0], 1);
    g_list[i0][pos0] = t * 2 + 0;
    g_p[t * 2 + 0] = p0;
    int pos1 = atomicAdd(&g_count[i1], 1);
    g_list[i1][pos1] = t * 2 + 1;
    g_p[t * 2 + 1] = p1;
}

// ================= up projection (fp16 mma, ldmatrix, 3-stage cp.async) =================
// CTA 128(M) x 64(N), BK=64 halves. 8 warps (4m x 2n), warp tile 32x32. Dual B.
// Stage: A 16KB + B1 8KB + B3 8KB = 32KB. 3 stages = 96KB.
#define UP_STG 32768
__global__ __launch_bounds__(256) void moe_up_h(const __half* __restrict__ w1t,
                                                const __half* __restrict__ w3t,
                                                int routed) {
    extern __shared__ char dsm[];
    __shared__ int sSlot[128];
    __shared__ int sTok[128];

    int e = blockIdx.z;
    int M = routed ? g_count[e] : T_TOK;
    int row0 = blockIdx.x * 128;
    if (row0 >= M) return;
    int col0 = blockIdx.y * 64;
    const __half* W1 = w1t + (size_t)e * HIDSZ * DIMSZ;   // [H][D]
    const __half* W3 = w3t + (size_t)e * HIDSZ * DIMSZ;
    __half* hout = routed ? g_h : g_hs;

    uint32_t base = smem_u32(dsm);

    int tid = threadIdx.x, lane = tid & 31, warp = tid >> 5;
    if (tid < 128) {
        int r = row0 + tid;
        int sl = (r < M) ? (routed ? g_list[e][r] : r) : -1;
        sSlot[tid] = sl;
        sTok[tid] = (sl < 0) ? 0 : (routed ? (sl >> 1) : sl);
    }
    __syncthreads();

    int wm = warp >> 1, wc = warp & 1;
    int wr0 = wm * 32, wn0 = wc * 32;

    int ar = tid >> 3, ac = tid & 7;            // A: 128 rows x 8 chunks, 4/thread
    int bn = tid >> 3, bc = tid & 7;            // B: 64 rows x 8 chunks, 2/thread each

    auto loadStage = [&](int st, int ch) {
        uint32_t sb = base + st * UP_STG;
#pragma unroll
        for (int j = 0; j < 4; j++) {
            int row = ar + j * 32;
            uint32_t sw = swz(row * 128 + ac * 16);
            cp16(sb + sw, g_xh + (size_t)sTok[row] * DIMSZ + ch * 64 + ac * 8);
        }
#pragma unroll
        for (int j = 0; j < 2; j++) {
            int n = bn + j * 32;
            uint32_t sw = swz(n * 128 + bc * 16);
            cp16(sb + 16384 + sw, W1 + (size_t)(col0 + n) * DIMSZ + ch * 64 + bc * 8);
            cp16(sb + 24576 + sw, W3 + (size_t)(col0 + n) * DIMSZ + ch * 64 + bc * 8);
        }
    };

    float acc1[2][4][4] = {};
    float acc3[2][4][4] = {};

    const int nCh = DIMSZ / 64;   // 8
    loadStage(0, 0); CP_COMMIT();
    loadStage(1, 1); CP_COMMIT();

    int aRowF = (lane & 15);
    int aColF = (lane >> 4) << 3;
    int bRowF = ((lane >> 4) << 3) + (lane & 7);
    int bColF = ((lane >> 3) & 1) << 3;

    for (int c = 0; c < nCh; c++) {
        int s = c % 3;
        if (c + 2 < nCh) {
            loadStage((c + 2) % 3, c + 2);
            CP_COMMIT();
            CP_WAIT(2);
        } else {
            CP_WAIT(0);
        }
        __syncthreads();

        uint32_t sA = base + s * UP_STG;
        uint32_t sB1 = sA + 16384;
        uint32_t sB3 = sA + 24576;
#pragma unroll
        for (int kk = 0; kk < 4; kk++) {
            uint32_t a[2][4], b1[2][4], b3[2][4];
#pragma unroll
            for (int ma = 0; ma < 2; ma++) {
                int row = wr0 + ma * 16 + aRowF;
                uint32_t off = swz(row * 128 + (kk * 16 + aColF) * 2);
                LDSM4(a[ma], sA + off);
            }
#pragma unroll
            for (int nb = 0; nb < 2; nb++) {
                int row = wn0 + nb * 16 + bRowF;
                uint32_t off = swz(row * 128 + (kk * 16 + bColF) * 2);
                LDSM4(b1[nb], sB1 + off);
                LDSM4(b3[nb], sB3 + off);
            }
#pragma unroll
            for (int ma = 0; ma < 2; ma++) {
#pragma unroll
                for (int nb = 0; nb < 2; nb++) {
#pragma unroll
                    for (int h = 0; h < 2; h++) {
                        MMA16816(acc1[ma][nb * 2 + h], a[ma], b1[nb][2 * h], b1[nb][2 * h + 1]);
                        MMA16816(acc3[ma][nb * 2 + h], a[ma], b3[nb][2 * h], b3[nb][2 * h + 1]);
                    }
                }
            }
        }
        __syncthreads();
    }

    // epilogue: silu(acc1)*acc3 -> fp16 direct store
    int cRow = lane >> 2, cCol = (lane & 3) * 2;
#pragma unroll
    for (int ma = 0; ma < 2; ma++) {
#pragma unroll
        for (int half = 0; half < 2; half++) {
            int rl = wr0 + ma * 16 + half * 8 + cRow;
            int slot = sSlot[rl];
            if (slot < 0) continue;
            __half* hp = hout + (size_t)slot * HIDSZ + col0 + wn0;
#pragma unroll
            for (int na = 0; na < 4; na++) {
                float u0 = acc1[ma][na][half * 2 + 0];
                float u1 = acc1[ma][na][half * 2 + 1];
                float v0 = acc3[ma][na][half * 2 + 0];
                float v1 = acc3[ma][na][half * 2 + 1];
                float o0 = (u0 / (1.f + expf(-u0))) * v0;
                float o1 = (u1 / (1.f + expf(-u1))) * v1;
                *(__half2*)(hp + na * 8 + cCol) = __floats2half2_rn(o0, o1);
            }
        }
    }
}

// ================= down projection (fp16 mma, ldmatrix, 3-stage cp.async) =================
// CTA 128(M) x 128(N), BK=64. 8 warps (2m x 4n), warp tile 64x32.
// Stage: A 16KB + B 16KB = 32KB. 3 stages = 96KB.
#define DN_STG 32768
__global__ __launch_bounds__(256) void moe_down_h(const __half* __restrict__ w2t,
                                                  float* __restrict__ out,
                                                  int routed) {
    extern __shared__ char dsm[];
    __shared__ int sSlot[128];

    int e = blockIdx.z;
    int M = routed ? g_count[e] : T_TOK;
    int row0 = blockIdx.x * 128;
    if (row0 >= M) return;
    int col0 = blockIdx.y * 128;
    const __half* W2 = w2t + (size_t)e * DIMSZ * HIDSZ;   // [D][H]
    const __half* hin = routed ? g_h : g_hs;
    float* yout = routed ? g_ys : out;

    uint32_t base = smem_u32(dsm);

    int tid = threadIdx.x, lane = tid & 31, warp = tid >> 5;
    if (tid < 128) {
        int r = row0 + tid;
        sSlot[tid] = (r < M) ? (routed ? g_list[e][r] : r) : -1;
    }
    __syncthreads();

    int wm = warp >> 2, wc = warp & 3;
    int wr0 = wm * 64, wn0 = wc * 32;

    int ar = tid >> 3, ac = tid & 7;

    auto loadStage = [&](int st, int ch) {
        uint32_t sb = base + st * DN_STG;
#pragma unroll
        for (int j = 0; j < 4; j++) {
            int row = ar + j * 32;
            uint32_t sw = swz(row * 128 + ac * 16);
            int sl = sSlot[row];
            int arow = (sl < 0) ? 0 : sl;
            cp16(sb + sw, hin + (size_t)arow * HIDSZ + ch * 64 + ac * 8);
            cp16(sb + 16384 + sw, W2 + (size_t)(col0 + row) * HIDSZ + ch * 64 + ac * 8);
        }
    };

    float acc[4][4][4] = {};

    const int nCh = HIDSZ / 64;   // 16
    loadStage(0, 0); CP_COMMIT();
    loadStage(1, 1); CP_COMMIT();

    int aRowF = (lane & 15);
    int aColF = (lane >> 4) << 3;
    int bRowF = ((lane >> 4) << 3) + (lane & 7);
    int bColF = ((lane >> 3) & 1) << 3;

    for (int c = 0; c < nCh; c++) {
        int s = c % 3;
        if (c + 2 < nCh) {
            loadStage((c + 2) % 3, c + 2);
            CP_COMMIT();
            CP_WAIT(2);
        } else {
            CP_WAIT(0);
        }
        __syncthreads();

        uint32_t sA = base + s * DN_STG;
        uint32_t sB = sA + 16384;
#pragma unroll
        for (int kk = 0; kk < 4; kk++) {
            uint32_t a[4][4], b[2][4];
#pragma unroll
            for (int ma = 0; ma < 4; ma++) {
                int row = wr0 + ma * 16 + aRowF;
                uint32_t off = swz(row * 128 + (kk * 16 + aColF) * 2);
                LDSM4(a[ma], sA + off);
            }
#pragma unroll
            for (int nb = 0; nb < 2; nb++) {
                int row = wn0 + nb * 16 + bRowF;
                uint32_t off = swz(row * 128 + (kk * 16 + bColF) * 2);
                LDSM4(b[nb], sB + off);
            }
#pragma unroll
            for (int ma = 0; ma < 4; ma++) {
#pragma unroll
                for (int nb = 0; nb < 2; nb++) {
#pragma unroll
                    for (int h = 0; h < 2; h++) {
                        MMA16816(acc[ma][nb * 2 + h], a[ma], b[nb][2 * h], b[nb][2 * h + 1]);
                    }
                }
            }
        }
        __syncthreads();
    }

    int cRow = lane >> 2, cCol = (lane & 3) * 2;
#pragma unroll
    for (int ma = 0; ma < 4; ma++) {
#pragma unroll
        for (int half = 0; half < 2; half++) {
            int rl = wr0 + ma * 16 + half * 8 + cRow;
            int slot = sSlot[rl];
            if (slot < 0) continue;
            float scale = routed ? g_p[slot] : 1.f;
            float* yp = yout + (size_t)slot * DIMSZ + col0 + wn0;
#pragma unroll
            for (int na = 0; na < 4; na++) {
                float2 o;
                o.x = scale * acc[ma][na][half * 2 + 0];
                o.y = scale * acc[ma][na][half * 2 + 1];
                *(float2*)(yp + na * 8 + cCol) = o;
            }
        }
    }
}

// ---------------- combine ----------------
__global__ void combine_kernel(float* __restrict__ out) {
    int idx = blockIdx.x * blockDim.x + threadIdx.x;
    const int n4 = T_TOK * DIMSZ / 4;
    if (idx >= n4) return;
    int dim4 = DIMSZ / 4;
    int t = idx / dim4;
    int d = idx % dim4;
    float4 o  = ((float4*)out)[idx];
    float4 y0 = ((const float4*)g_ys)[(size_t)(2 * t) * dim4 + d];
    float4 y1 = ((const float4*)g_ys)[(size_t)(2 * t + 1) * dim4 + d];
    o.x += y0.x + y1.x;
    o.y += y0.y + y1.y;
    o.z += y0.z + y1.z;
    o.w += y0.w + y1.w;
    ((float4*)out)[idx] = o;
}

// ---------------- launcher ----------------
extern "C" void kernel_launch(void* const* d_in, const int* in_sizes, int n_in,
                              void* d_out, int out_size) {
    const float* x      = (const float*)d_in[0];
    const float* gate_w = (const float*)d_in[1];
    const float* biases = (const float*)d_in[2];
    const float* w1     = (const float*)d_in[3];
    const float* w3     = (const float*)d_in[4];
    const float* w2     = (const float*)d_in[5];
    const float* sw1    = (const float*)d_in[6];
    const float* sw3    = (const float*)d_in[7];
    const float* sw2    = (const float*)d_in[8];
    float* out          = (float*)d_out;

    const int upSmem = 3 * UP_STG;   // 98304
    const int dnSmem = 3 * DN_STG;   // 98304
    cudaFuncSetAttribute(moe_up_h,   cudaFuncAttributeMaxDynamicSharedMemorySize, upSmem);
    cudaFuncSetAttribute(moe_down_h, cudaFuncAttributeMaxDynamicSharedMemorySize, dnSmem);

    __half *xh, *w1t, *w3t, *w2t, *sw1t, *sw3t, *sw2t;
    cudaGetSymbolAddress((void**)&xh,   g_xh);
    cudaGetSymbolAddress((void**)&w1t,  g_w1t);
    cudaGetSymbolAddress((void**)&w3t,  g_w3t);
    cudaGetSymbolAddress((void**)&w2t,  g_w2t);
    cudaGetSymbolAddress((void**)&sw1t, g_sw1t);
    cudaGetSymbolAddress((void**)&sw3t, g_sw3t);
    cudaGetSymbolAddress((void**)&sw2t, g_sw2t);

    reset_counts_kernel<<<1, 32>>>();
    router_kernel<<<T_TOK / 8, 256>>>(x, gate_w, biases);

    // operand prep
    cvt_h_kernel<<<(T_TOK * DIMSZ / 4 + 255) / 256, 256>>>(x, xh, T_TOK * DIMSZ / 4);
    dim3 tb(32, 8);
    transpose_h_kernel<<<dim3(HIDSZ / 32, DIMSZ / 32, NE), tb>>>(w1, w1t, DIMSZ, HIDSZ);
    transpose_h_kernel<<<dim3(HIDSZ / 32, DIMSZ / 32, NE), tb>>>(w3, w3t, DIMSZ, HIDSZ);
    transpose_h_kernel<<<dim3(DIMSZ / 32, HIDSZ / 32, NE), tb>>>(w2, w2t, HIDSZ, DIMSZ);
    transpose_h_kernel<<<dim3(HIDSZ / 32, DIMSZ / 32, 1), tb>>>(sw1, sw1t, DIMSZ, HIDSZ);
    transpose_h_kernel<<<dim3(HIDSZ / 32, DIMSZ / 32, 1), tb>>>(sw3, sw3t, DIMSZ, HIDSZ);
    transpose_h_kernel<<<dim3(DIMSZ / 32, HIDSZ / 32, 1), tb>>>(sw2, sw2t, HIDSZ, DIMSZ);

    // shared expert
    moe_up_h<<<dim3(T_TOK / 128, HIDSZ / 64, 1), 256, upSmem>>>(sw1t, sw3t, 0);
    moe_down_h<<<dim3(T_TOK / 128, DIMSZ / 128, 1), 256, dnSmem>>>(sw2t, out, 0);

    // routed experts
    moe_up_h<<<dim3(T_TOK / 128, HIDSZ / 64, NE), 256, upSmem>>>(w1t, w3t, 1);
    moe_down_h<<<dim3(T_TOK / 128, DIMSZ / 128, NE), 256, dnSmem>>>(w2t, out, 1);

    combine_kernel<<<(T_TOK * DIMSZ / 4 + 255) / 256, 256>>>(out);
}

// round 9
// speedup vs baseline: 7.4189x; 1.1567x over previous
#include <cuda_runtime.h>
#include <cuda_fp16.h>
#include <math.h>
#include <stdint.h>

#define T_TOK 8192
#define DIMSZ 512
#define HIDSZ 1024
#define NE    8

// ---------------- device scratch ----------------
__device__ int    g_count[NE];
__device__ int    g_list[NE][T_TOK];
__device__ float  g_p[T_TOK * 2];
__device__ __half g_h[(size_t)T_TOK * 2 * HIDSZ];
__device__ __half g_hs[(size_t)T_TOK * HIDSZ];
__device__ float  g_ys[(size_t)T_TOK * 2 * DIMSZ];

__device__ __half g_xh[(size_t)T_TOK * DIMSZ];
__device__ __half g_w1h[(size_t)NE * DIMSZ * HIDSZ];   // natural [E][D][H]
__device__ __half g_w3h[(size_t)NE * DIMSZ * HIDSZ];
__device__ __half g_w2h[(size_t)NE * HIDSZ * DIMSZ];   // natural [E][H][D]
__device__ __half g_sw1h[(size_t)DIMSZ * HIDSZ];
__device__ __half g_sw3h[(size_t)DIMSZ * HIDSZ];
__device__ __half g_sw2h[(size_t)HIDSZ * DIMSZ];

// ---------------- helpers ----------------
__device__ __forceinline__ uint32_t smem_u32(const void* p) {
    uint32_t a;
    asm("{ .reg .u64 t; cvta.to.shared.u64 t, %1; cvt.u32.u64 %0, t; }" : "=r"(a) : "l"(p));
    return a;
}
__device__ __forceinline__ void cp16(uint32_t saddr, const void* g) {
    asm volatile("cp.async.cg.shared.global [%0], [%1], 16;" :: "r"(saddr), "l"(g));
}
#define CP_COMMIT()  asm volatile("cp.async.commit_group;")
#define CP_WAIT(N)   asm volatile("cp.async.wait_group %0;" :: "n"(N))

#define LDSM4(R, addr)                                                          \
    asm volatile("ldmatrix.sync.aligned.m8n8.x4.shared.b16 {%0,%1,%2,%3}, [%4];"\
        : "=r"((R)[0]), "=r"((R)[1]), "=r"((R)[2]), "=r"((R)[3]) : "r"(addr))

#define LDSM4T(R, addr)                                                         \
    asm volatile("ldmatrix.sync.aligned.m8n8.x4.trans.shared.b16 {%0,%1,%2,%3}, [%4];"\
        : "=r"((R)[0]), "=r"((R)[1]), "=r"((R)[2]), "=r"((R)[3]) : "r"(addr))

#define MMA16816(C, A, B0, B1)                                                  \
    asm volatile(                                                               \
        "mma.sync.aligned.m16n8k16.row.col.f32.f16.f16.f32 "                    \
        "{%0,%1,%2,%3}, {%4,%5,%6,%7}, {%8,%9}, {%0,%1,%2,%3};"                 \
        : "+f"((C)[0]), "+f"((C)[1]), "+f"((C)[2]), "+f"((C)[3])                 \
        : "r"((A)[0]), "r"((A)[1]), "r"((A)[2]), "r"((A)[3]), "r"(B0), "r"(B1))

__device__ __forceinline__ uint32_t swz(uint32_t off) {   // SW128 (Swizzle<3,4,3>)
    return off ^ ((off >> 3) & 0x70);
}

// ---------------- small kernels ----------------
__global__ void reset_counts_kernel() {
    if (threadIdx.x < NE) g_count[threadIdx.x] = 0;
}

__global__ void cvt_h_kernel(const float* __restrict__ in, __half* __restrict__ out, int n4) {
    int i = blockIdx.x * blockDim.x + threadIdx.x;
    if (i >= n4) return;
    float4 v = ((const float4*)in)[i];
    __half2* o = reinterpret_cast<__half2*>(out) + 2 * i;
    o[0] = __floats2half2_rn(v.x, v.y);
    o[1] = __floats2half2_rn(v.z, v.w);
}

__global__ void router_kernel(const float* __restrict__ x,
                              const float* __restrict__ gw,
                              const float* __restrict__ biases) {
    int warp = (blockIdx.x * blockDim.x + threadIdx.x) >> 5;
    int lane = threadIdx.x & 31;
    if (warp >= T_TOK) return;
    const float* xt = x + (size_t)warp * DIMSZ;

    float sc[NE];
#pragma unroll
    for (int e = 0; e < NE; e++) sc[e] = 0.f;
    for (int i = lane; i < DIMSZ; i += 32) {
        float xv = xt[i];
#pragma unroll
        for (int e = 0; e < NE; e++) sc[e] += xv * gw[e * DIMSZ + i];
    }
#pragma unroll
    for (int e = 0; e < NE; e++) {
#pragma unroll
        for (int off = 16; off; off >>= 1)
            sc[e] += __shfl_xor_sync(0xffffffffu, sc[e], off);
    }
    if (lane != 0) return;

    float b[NE];
#pragma unroll
    for (int e = 0; e < NE; e++) b[e] = sc[e] + biases[e];
    int i0 = 0;
#pragma unroll
    for (int e = 1; e < NE; e++) if (b[e] > b[i0]) i0 = e;
    int i1 = (i0 == 0) ? 1 : 0;
#pragma unroll
    for (int e = 0; e < NE; e++) if (e != i0 && b[e] > b[i1]) i1 = e;

    int a0 = 0;
#pragma unroll
    for (int e = 1; e < NE; e++) if (sc[e] > sc[a0]) a0 = e;
    int a1 = (a0 == 0) ? 1 : 0;
#pragma unroll
    for (int e = 0; e < NE; e++) if (e != a0 && sc[e] > sc[a1]) a1 = e;

    float p0 = 1.f / (1.f + expf(-sc[a0]));
    float p1 = 1.f / (1.f + expf(-sc[a1]));
    float s = p0 + p1;
    p0 /= s; p1 /= s;

    int t = warp;
    int pos0 = atomicAdd(&g_count[i0], 1);
    g_list[i0][pos0] = t * 2 + 0;
    g_p[t * 2 + 0] = p0;
    int pos1 = atomicAdd(&g_count[i1], 1);
    g_list[i1][pos1] = t * 2 + 1;
    g_p[t * 2 + 1] = p1;
}

// ================= up projection =================
// CTA 128(M) x 64(N), BK=64. 8 warps (4m x 2n), warp tile 32x32, dual B (w1,w3).
// B tiles from NATURAL [D][H] layout (rows = k), fragments via ldmatrix.trans.
// Stage: A 16KB + B1 8KB + B3 8KB = 32KB; 3 stages = 96KB. z-slice NE = shared expert.
#define UP_STG 32768
__global__ __launch_bounds__(256, 2) void moe_up_h(const __half* __restrict__ w1h,
                                                   const __half* __restrict__ w3h,
                                                   const __half* __restrict__ sw1h,
                                                   const __half* __restrict__ sw3h) {
    extern __shared__ char dsm[];
    __shared__ int sSlot[128];
    __shared__ int sTok[128];

    int e = blockIdx.z;
    bool shared_e = (e == NE);
    int M = shared_e ? T_TOK : g_count[e];
    int row0 = blockIdx.x * 128;
    if (row0 >= M) return;
    int col0 = blockIdx.y * 64;
    const __half* W1 = shared_e ? sw1h : (w1h + (size_t)e * DIMSZ * HIDSZ);   // [D][H]
    const __half* W3 = shared_e ? sw3h : (w3h + (size_t)e * DIMSZ * HIDSZ);
    __half* hout = shared_e ? g_hs : g_h;

    uint32_t base = smem_u32(dsm);

    int tid = threadIdx.x, lane = tid & 31, warp = tid >> 5;
    if (tid < 128) {
        int r = row0 + tid;
        int sl = (r < M) ? (shared_e ? r : g_list[e][r]) : -1;
        sSlot[tid] = sl;
        sTok[tid] = (sl < 0) ? 0 : (shared_e ? sl : (sl >> 1));
    }
    __syncthreads();

    int wm = warp >> 1, wc = warp & 1;
    int wr0 = wm * 32, wn0 = wc * 32;

    int ar = tid >> 3, ac = tid & 7;     // A: 128 rows x 8 chunks, 4/thread
    int bk = tid >> 3, bc = tid & 7;     // B: 64 k-rows x 8 chunks, 2/thread each matrix

    auto loadStage = [&](int st, int ch) {
        uint32_t sb = base + st * UP_STG;
#pragma unroll
        for (int j = 0; j < 4; j++) {
            int row = ar + j * 32;
            uint32_t sw = swz(row * 128 + ac * 16);
            cp16(sb + sw, g_xh + (size_t)sTok[row] * DIMSZ + ch * 64 + ac * 8);
        }
#pragma unroll
        for (int j = 0; j < 2; j++) {
            int kr = bk + j * 32;
            uint32_t sw = swz(kr * 128 + bc * 16);
            cp16(sb + 16384 + sw, W1 + (size_t)(ch * 64 + kr) * HIDSZ + col0 + bc * 8);
            cp16(sb + 24576 + sw, W3 + (size_t)(ch * 64 + kr) * HIDSZ + col0 + bc * 8);
        }
    };

    float acc1[2][4][4] = {};
    float acc3[2][4][4] = {};

    const int nCh = DIMSZ / 64;   // 8
    loadStage(0, 0); CP_COMMIT();
    loadStage(1, 1); CP_COMMIT();

    int aRowF = (lane & 15);
    int aColF = (lane >> 4) << 3;
    int bKF = (lane & 7) + ((lane >> 3) & 1) * 8;    // k row within 16-block
    int bNF = ((lane >> 4) & 1) * 8;                 // n half offset

    for (int c = 0; c < nCh; c++) {
        int s = c % 3;
        if (c + 2 < nCh) {
            loadStage((c + 2) % 3, c + 2);
            CP_COMMIT();
            CP_WAIT(2);
        } else {
            CP_WAIT(0);
        }
        __syncthreads();

        uint32_t sA = base + s * UP_STG;
        uint32_t sB1 = sA + 16384;
        uint32_t sB3 = sA + 24576;
#pragma unroll
        for (int kk = 0; kk < 4; kk++) {
            uint32_t a[2][4], b1[2][4], b3[2][4];
#pragma unroll
            for (int ma = 0; ma < 2; ma++) {
                int row = wr0 + ma * 16 + aRowF;
                uint32_t off = swz(row * 128 + (kk * 16 + aColF) * 2);
                LDSM4(a[ma], sA + off);
            }
#pragma unroll
            for (int nb = 0; nb < 2; nb++) {
                uint32_t off = swz((kk * 16 + bKF) * 128 + (wn0 + nb * 16 + bNF) * 2);
                LDSM4T(b1[nb], sB1 + off);
                LDSM4T(b3[nb], sB3 + off);
            }
#pragma unroll
            for (int ma = 0; ma < 2; ma++) {
#pragma unroll
                for (int nb = 0; nb < 2; nb++) {
#pragma unroll
                    for (int h = 0; h < 2; h++) {
                        MMA16816(acc1[ma][nb * 2 + h], a[ma], b1[nb][2 * h], b1[nb][2 * h + 1]);
                        MMA16816(acc3[ma][nb * 2 + h], a[ma], b3[nb][2 * h], b3[nb][2 * h + 1]);
                    }
                }
            }
        }
        __syncthreads();
    }

    // epilogue: silu(acc1)*acc3 -> fp16 store
    int cRow = lane >> 2, cCol = (lane & 3) * 2;
#pragma unroll
    for (int ma = 0; ma < 2; ma++) {
#pragma unroll
        for (int half = 0; half < 2; half++) {
            int rl = wr0 + ma * 16 + half * 8 + cRow;
            int slot = sSlot[rl];
            if (slot < 0) continue;
            __half* hp = hout + (size_t)slot * HIDSZ + col0 + wn0;
#pragma unroll
            for (int na = 0; na < 4; na++) {
                float u0 = acc1[ma][na][half * 2 + 0];
                float u1 = acc1[ma][na][half * 2 + 1];
                float v0 = acc3[ma][na][half * 2 + 0];
                float v1 = acc3[ma][na][half * 2 + 1];
                float o0 = (u0 / (1.f + expf(-u0))) * v0;
                float o1 = (u1 / (1.f + expf(-u1))) * v1;
                *(__half2*)(hp + na * 8 + cCol) = __floats2half2_rn(o0, o1);
            }
        }
    }
}

// ================= down projection =================
// CTA 128(M) x 128(N), BK=64. 8 warps (2m x 4n), warp tile 64x32.
// B from NATURAL [H][D] layout: two 64-wide panels (rows = k, 128B rows), ldmatrix.trans.
// Stage: A 16KB + B 16KB = 32KB; 3 stages = 96KB. z-slice NE = shared expert -> out.
#define DN_STG 32768
__global__ __launch_bounds__(256, 2) void moe_down_h(const __half* __restrict__ w2h,
                                                     const __half* __restrict__ sw2h,
                                                     float* __restrict__ out) {
    extern __shared__ char dsm[];
    __shared__ int sSlot[128];

    int e = blockIdx.z;
    bool shared_e = (e == NE);
    int M = shared_e ? T_TOK : g_count[e];
    int row0 = blockIdx.x * 128;
    if (row0 >= M) return;
    int col0 = blockIdx.y * 128;
    const __half* W2 = shared_e ? sw2h : (w2h + (size_t)e * HIDSZ * DIMSZ);   // [H][D]
    const __half* hin = shared_e ? g_hs : g_h;
    float* yout = shared_e ? out : g_ys;

    uint32_t base = smem_u32(dsm);

    int tid = threadIdx.x, lane = tid & 31, warp = tid >> 5;
    if (tid < 128) {
        int r = row0 + tid;
        sSlot[tid] = (r < M) ? (shared_e ? r : g_list[e][r]) : -1;
    }
    __syncthreads();

    int wm = warp >> 2, wc = warp & 3;
    int wr0 = wm * 64, wn0 = wc * 32;
    int panel = wn0 >> 6;              // 0 or 1
    int wnp = wn0 & 63;                // n offset within panel

    int ar = tid >> 3, ac = tid & 7;

    auto loadStage = [&](int st, int ch) {
        uint32_t sb = base + st * DN_STG;
#pragma unroll
        for (int j = 0; j < 4; j++) {
            int row = ar + j * 32;
            uint32_t sw = swz(row * 128 + ac * 16);
            int sl = sSlot[row];
            int arow = (sl < 0) ? 0 : sl;
            cp16(sb + sw, hin + (size_t)arow * HIDSZ + ch * 64 + ac * 8);
        }
        // B: 64 k-rows x 2 panels x 8 chunks = 1024 chunks, 4/thread
#pragma unroll
        for (int j = 0; j < 4; j++) {
            int idx = tid + j * 256;
            int pnl = idx >> 9;            // 0..1
            int rem = idx & 511;
            int kr = rem >> 3;             // 0..63
            int nc = rem & 7;              // 16B chunk
            uint32_t sw = swz(kr * 128 + nc * 16);
            cp16(sb + 16384 + pnl * 8192 + sw,
                 W2 + (size_t)(ch * 64 + kr) * DIMSZ + col0 + pnl * 64 + nc * 8);
        }
    };

    float acc[4][4][4] = {};

    const int nCh = HIDSZ / 64;   // 16
    loadStage(0, 0); CP_COMMIT();
    loadStage(1, 1); CP_COMMIT();

    int aRowF = (lane & 15);
    int aColF = (lane >> 4) << 3;
    int bKF = (lane & 7) + ((lane >> 3) & 1) * 8;
    int bNF = ((lane >> 4) & 1) * 8;

    for (int c = 0; c < nCh; c++) {
        int s = c % 3;
        if (c + 2 < nCh) {
            loadStage((c + 2) % 3, c + 2);
            CP_COMMIT();
            CP_WAIT(2);
        } else {
            CP_WAIT(0);
        }
        __syncthreads();

        uint32_t sA = base + s * DN_STG;
        uint32_t sB = sA + 16384 + panel * 8192;
#pragma unroll
        for (int kk = 0; kk < 4; kk++) {
            uint32_t a[4][4], b[2][4];
#pragma unroll
            for (int ma = 0; ma < 4; ma++) {
                int row = wr0 + ma * 16 + aRowF;
                uint32_t off = swz(row * 128 + (kk * 16 + aColF) * 2);
                LDSM4(a[ma], sA + off);
            }
#pragma unroll
            for (int nb = 0; nb < 2; nb++) {
                uint32_t off = swz((kk * 16 + bKF) * 128 + (wnp + nb * 16 + bNF) * 2);
                LDSM4T(b[nb], sB + off);
            }
#pragma unroll
            for (int ma = 0; ma < 4; ma++) {
#pragma unroll
                for (int nb = 0; nb < 2; nb++) {
#pragma unroll
                    for (int h = 0; h < 2; h++) {
                        MMA16816(acc[ma][nb * 2 + h], a[ma], b[nb][2 * h], b[nb][2 * h + 1]);
                    }
                }
            }
        }
        __syncthreads();
    }

    int cRow = lane >> 2, cCol = (lane & 3) * 2;
#pragma unroll
    for (int ma = 0; ma < 4; ma++) {
#pragma unroll
        for (int half = 0; half < 2; half++) {
            int rl = wr0 + ma * 16 + half * 8 + cRow;
            int slot = sSlot[rl];
            if (slot < 0) continue;
            float scale = shared_e ? 1.f : g_p[slot];
            float* yp = yout + (size_t)slot * DIMSZ + col0 + wn0;
#pragma unroll
            for (int na = 0; na < 4; na++) {
                float2 o;
                o.x = scale * acc[ma][na][half * 2 + 0];
                o.y = scale * acc[ma][na][half * 2 + 1];
                *(float2*)(yp + na * 8 + cCol) = o;
            }
        }
    }
}

// ---------------- combine ----------------
__global__ void combine_kernel(float* __restrict__ out) {
    int idx = blockIdx.x * blockDim.x + threadIdx.x;
    const int n4 = T_TOK * DIMSZ / 4;
    if (idx >= n4) return;
    int dim4 = DIMSZ / 4;
    int t = idx / dim4;
    int d = idx % dim4;
    float4 o  = ((float4*)out)[idx];
    float4 y0 = ((const float4*)g_ys)[(size_t)(2 * t) * dim4 + d];
    float4 y1 = ((const float4*)g_ys)[(size_t)(2 * t + 1) * dim4 + d];
    o.x += y0.x + y1.x;
    o.y += y0.y + y1.y;
    o.z += y0.z + y1.z;
    o.w += y0.w + y1.w;
    ((float4*)out)[idx] = o;
}

// ---------------- launcher ----------------
extern "C" void kernel_launch(void* const* d_in, const int* in_sizes, int n_in,
                              void* d_out, int out_size) {
    const float* x      = (const float*)d_in[0];
    const float* gate_w = (const float*)d_in[1];
    const float* biases = (const float*)d_in[2];
    const float* w1     = (const float*)d_in[3];
    const float* w3     = (const float*)d_in[4];
    const float* w2     = (const float*)d_in[5];
    const float* sw1    = (const float*)d_in[6];
    const float* sw3    = (const float*)d_in[7];
    const float* sw2    = (const float*)d_in[8];
    float* out          = (float*)d_out;

    const int upSmem = 3 * UP_STG;   // 98304
    const int dnSmem = 3 * DN_STG;   // 98304
    cudaFuncSetAttribute(moe_up_h,   cudaFuncAttributeMaxDynamicSharedMemorySize, upSmem);
    cudaFuncSetAttribute(moe_down_h, cudaFuncAttributeMaxDynamicSharedMemorySize, dnSmem);

    __half *xh, *w1h, *w3h, *w2h, *sw1h, *sw3h, *sw2h;
    cudaGetSymbolAddress((void**)&xh,   g_xh);
    cudaGetSymbolAddress((void**)&w1h,  g_w1h);
    cudaGetSymbolAddress((void**)&w3h,  g_w3h);
    cudaGetSymbolAddress((void**)&w2h,  g_w2h);
    cudaGetSymbolAddress((void**)&sw1h, g_sw1h);
    cudaGetSymbolAddress((void**)&sw3h, g_sw3h);
    cudaGetSymbolAddress((void**)&sw2h, g_sw2h);

    reset_counts_kernel<<<1, 32>>>();
    router_kernel<<<T_TOK / 8, 256>>>(x, gate_w, biases);

    // operand prep: straight fp32 -> fp16 (no transposes)
    cvt_h_kernel<<<(T_TOK * DIMSZ / 4 + 255) / 256, 256>>>(x, xh, T_TOK * DIMSZ / 4);
    cvt_h_kernel<<<(NE * DIMSZ * HIDSZ / 4 + 255) / 256, 256>>>(w1, w1h, NE * DIMSZ * HIDSZ / 4);
    cvt_h_kernel<<<(NE * DIMSZ * HIDSZ / 4 + 255) / 256, 256>>>(w3, w3h, NE * DIMSZ * HIDSZ / 4);
    cvt_h_kernel<<<(NE * HIDSZ * DIMSZ / 4 + 255) / 256, 256>>>(w2, w2h, NE * HIDSZ * DIMSZ / 4);
    cvt_h_kernel<<<(DIMSZ * HIDSZ / 4 + 255) / 256, 256>>>(sw1, sw1h, DIMSZ * HIDSZ / 4);
    cvt_h_kernel<<<(DIMSZ * HIDSZ / 4 + 255) / 256, 256>>>(sw3, sw3h, DIMSZ * HIDSZ / 4);
    cvt_h_kernel<<<(HIDSZ * DIMSZ / 4 + 255) / 256, 256>>>(sw2, sw2h, HIDSZ * DIMSZ / 4);

    // fused: routed experts (z=0..7) + shared expert (z=8)
    moe_up_h<<<dim3(T_TOK / 128, HIDSZ / 64, NE + 1), 256, upSmem>>>(w1h, w3h, sw1h, sw3h);
    moe_down_h<<<dim3(T_TOK / 128, DIMSZ / 128, NE + 1), 256, dnSmem>>>(w2h, sw2h, out);

    combine_kernel<<<(T_TOK * DIMSZ / 4 + 255) / 256, 256>>>(out);
}